// round 9
// baseline (speedup 1.0000x reference)
#include <cuda_runtime.h>
#include <math.h>
#include <cstdint>

// B=8, A=1024, N=64, G=50, F=128
#define A_DIM 1024
#define F_DIM 128
#define G_DIM 50
#define K1STEPS 7          // GEMM1 K = 56 >= 50
#define LOG2F_CONST 0.6931471805599453f

// ---------------- device scratch ----------------
__device__ float g_xw[8 * A_DIM * F_DIM];     // x @ W_in2f  (4 MB)
__device__ float g_y [8 * A_DIM * F_DIM];     // pre-output  (4 MB)
__device__ float g_Wf1p[64 * F_DIM];          // W_f1 zero-padded to K=64, tf32-rounded
__device__ float g_Wf2p[F_DIM * F_DIM];       // W_f2 tf32-rounded

__device__ __forceinline__ float ssp(float x) {
    return fmaxf(x, 0.0f) + __logf(1.0f + __expf(-fabsf(x))) - LOG2F_CONST;
}
__device__ __forceinline__ float tf32r(float x) {
    uint32_t r;
    asm("cvt.rna.tf32.f32 %0, %1;" : "=r"(r) : "f"(x));
    return __uint_as_float(r);
}

// m16n8k8 row.col tf32 MMA. lane: gid=lane>>2, tig=lane&3
//   A: a0=(gid,tig) a1=(gid+8,tig) a2=(gid,tig+4) a3=(gid+8,tig+4)
//   B: b0=(k=tig,n=gid) b1=(k=tig+4,n=gid)
//   D: d0=(gid,2tig) d1=(gid,2tig+1) d2=(gid+8,2tig) d3=(gid+8,2tig+1)
__device__ __forceinline__ void mma8(float* d, const uint32_t* a, const uint32_t* b) {
    asm volatile(
        "mma.sync.aligned.m16n8k8.row.col.f32.tf32.tf32.f32 "
        "{%0,%1,%2,%3}, {%4,%5,%6,%7}, {%8,%9}, {%0,%1,%2,%3};"
        : "+f"(d[0]), "+f"(d[1]), "+f"(d[2]), "+f"(d[3])
        : "r"(a[0]), "r"(a[1]), "r"(a[2]), "r"(a[3]), "r"(b[0]), "r"(b[1]));
}

// ---------------- SMEM layout (one atom = 64 rows) ----------------
#define FS1 68            // f_ij row stride (floats), conflict-free A pattern
#define HS  132           // h row stride (floats), conflict-free A pattern
#define OFF_B1   0        // b_f1 [128]f
#define OFF_B2   512      // b_f2 [128]f
#define OFF_NBR  1024     // nbr  [64]i
#define OFF_MSK  1280     // mask [64]f
#define OFF_Y    1536     // y halves [256]f
#define OFF_FIJ  2560     // f_ij [64][68]f  = 17408 B
#define OFF_H    19968    // h/Wm [64][132]f = 33792 B
#define SMEM_TOTAL 53760

// ---------------------------------------------------------------------------
// prep: tf32-round + pad weights (natural [k][f] layout)
// ---------------------------------------------------------------------------
__global__ void prep_kernel(const float* __restrict__ W_f1, const float* __restrict__ W_f2) {
    int t = threadIdx.x;
    for (int i = t; i < 64 * F_DIM; i += blockDim.x) {
        int k = i >> 7;
        g_Wf1p[i] = (k < G_DIM) ? tf32r(W_f1[i]) : 0.0f;
    }
    for (int i = t; i < F_DIM * F_DIM; i += blockDim.x)
        g_Wf2p[i] = tf32r(W_f2[i]);
}

// ---------------------------------------------------------------------------
// dense: out[r, o] = (ssp?)(in[r,:] @ W[:,o] + bias)   — 8 rows per CTA
// ---------------------------------------------------------------------------
__global__ __launch_bounds__(F_DIM) void dense_kernel(
    const float* __restrict__ in, const float* __restrict__ W,
    const float* __restrict__ bias, float* __restrict__ outp, int apply_ssp)
{
    __shared__ float xs[8 * F_DIM];
    const int r0 = blockIdx.x * 8, o = threadIdx.x;
#pragma unroll
    for (int r = 0; r < 8; ++r)
        xs[r * F_DIM + o] = in[(size_t)(r0 + r) * F_DIM + o];
    __syncthreads();

    float a[8];
    float bb = bias ? __ldg(&bias[o]) : 0.0f;
#pragma unroll
    for (int r = 0; r < 8; ++r) a[r] = bb;
#pragma unroll 4
    for (int c = 0; c < F_DIM; ++c) {
        float w = __ldg(&W[c * F_DIM + o]);
#pragma unroll
        for (int r = 0; r < 8; ++r)
            a[r] = fmaf(xs[r * F_DIM + c], w, a[r]);
    }
#pragma unroll
    for (int r = 0; r < 8; ++r)
        outp[(size_t)(r0 + r) * F_DIM + o] = apply_ssp ? ssp(a[r]) : a[r];
}

// ---------------------------------------------------------------------------
// Main: ONE atom per CTA (64 neighbor rows), 256 threads, 8 warps (4M x 2N).
// Each warp: one 16-row M-tile x 64 cols -> 8 accumulator fragments (32 regs).
// 52.5 KB SMEM + reg cap 85 -> 3 CTAs/SM (24 warps/SM).
// ---------------------------------------------------------------------------
__global__ __launch_bounds__(256, 3) void cfconv_mma(
    const float* __restrict__ f_ij,   // [B,A,N,G]
    const float* __restrict__ mask,   // [B,A,N]
    const int*   __restrict__ nbrs,   // [B,A,N]
    const float* __restrict__ b_f1,
    const float* __restrict__ b_f2)
{
    extern __shared__ char smem[];
    float* b1s    = (float*)(smem + OFF_B1);
    float* b2s    = (float*)(smem + OFF_B2);
    int*   nbr_sh = (int*)  (smem + OFF_NBR);
    float* msk_sh = (float*)(smem + OFF_MSK);
    float* y_sh   = (float*)(smem + OFF_Y);
    float* fij_s  = (float*)(smem + OFF_FIJ);
    float* h_s    = (float*)(smem + OFF_H);

    const int tid = threadIdx.x, wid = tid >> 5, lane = tid & 31;
    const int gid = lane >> 2, tig = lane & 3;
    const int c = blockIdx.x;          // atom index 0..8191
    const int b = c >> 10;             // batch

    if (tid < 128) {
        b1s[tid] = b_f1[tid];
        b2s[tid] = b_f2[tid];
    }
    if (tid < 64) {
        nbr_sh[tid] = nbrs[(size_t)c * 64 + tid];
        msk_sh[tid] = mask[(size_t)c * 64 + tid];
    }
    // stage f_ij tile [64 rows][56 cols used], tf32-rounded, zero-padded 50..55
    {
        const float* fb = f_ij + (size_t)c * 64 * G_DIM;
        for (int i = tid; i < 64 * 64; i += 256) {
            int r = i >> 6, cc = i & 63;
            if (cc < 56)
                fij_s[r * FS1 + cc] = (cc < G_DIM) ? tf32r(__ldg(fb + r * G_DIM + cc)) : 0.0f;
        }
    }
    __syncthreads();

    const int n0 = (wid & 3) * 16;     // warp's 16 rows
    const int f0 = (wid >> 2) * 64;    // warp's 64 cols

    // ================= GEMM1: K=56 (7 k-steps) =================
    float acc[8][4];
#pragma unroll
    for (int t = 0; t < 8; ++t) { acc[t][0]=acc[t][1]=acc[t][2]=acc[t][3]=0.f; }

    {
        const uint32_t* fij_u = (const uint32_t*)fij_s;
#pragma unroll
        for (int ks = 0; ks < K1STEPS; ++ks) {
            const int k0 = ks * 8;
            uint32_t a[4], bf[8][2];
            {
                int r = (n0 + gid) * FS1 + k0 + tig;
                a[0] = fij_u[r];
                a[1] = fij_u[r + 8 * FS1];
                a[2] = fij_u[r + 4];
                a[3] = fij_u[r + 8 * FS1 + 4];
            }
#pragma unroll
            for (int ni = 0; ni < 8; ++ni) {
                int col = f0 + ni * 8 + gid;
                bf[ni][0] = __float_as_uint(__ldg(&g_Wf1p[(k0 + tig)     * F_DIM + col]));
                bf[ni][1] = __float_as_uint(__ldg(&g_Wf1p[(k0 + tig + 4) * F_DIM + col]));
            }
#pragma unroll
            for (int ni = 0; ni < 8; ++ni)
                mma8(acc[ni], a, bf[ni]);
        }
    }

    // ---- epi1: h = tf32(ssp(D1 + b1)) -> linear SMEM ----
#pragma unroll
    for (int ni = 0; ni < 8; ++ni) {
        float* d = acc[ni];
        int f = f0 + ni * 8 + 2 * tig;
        int n = n0 + gid;
        float bb0 = b1s[f], bb1 = b1s[f + 1];
        float2 v0 = make_float2(tf32r(ssp(d[0] + bb0)), tf32r(ssp(d[1] + bb1)));
        float2 v1 = make_float2(tf32r(ssp(d[2] + bb0)), tf32r(ssp(d[3] + bb1)));
        *(float2*)&h_s[n * HS + f]       = v0;
        *(float2*)&h_s[(n + 8) * HS + f] = v1;
    }
    __syncthreads();

    // ================= GEMM2: K=128 (16 k-steps) =================
#pragma unroll
    for (int t = 0; t < 8; ++t) { acc[t][0]=acc[t][1]=acc[t][2]=acc[t][3]=0.f; }

    {
        const uint32_t* h_u = (const uint32_t*)h_s;
#pragma unroll
        for (int ks = 0; ks < 16; ++ks) {
            const int k0 = ks * 8;
            uint32_t a[4], bf[8][2];
            {
                int r = (n0 + gid) * HS + k0 + tig;
                a[0] = h_u[r];
                a[1] = h_u[r + 8 * HS];
                a[2] = h_u[r + 4];
                a[3] = h_u[r + 8 * HS + 4];
            }
#pragma unroll
            for (int ni = 0; ni < 8; ++ni) {
                int col = f0 + ni * 8 + gid;
                bf[ni][0] = __float_as_uint(__ldg(&g_Wf2p[(k0 + tig)     * F_DIM + col]));
                bf[ni][1] = __float_as_uint(__ldg(&g_Wf2p[(k0 + tig + 4) * F_DIM + col]));
            }
#pragma unroll
            for (int ni = 0; ni < 8; ++ni)
                mma8(acc[ni], a, bf[ni]);
        }
    }
    __syncthreads();   // all warps done reading h before overwrite

    // ---- epi2: Wm = (D2 + b2) * mask -> linear SMEM (reuse h region) ----
#pragma unroll
    for (int ni = 0; ni < 8; ++ni) {
        float* d = acc[ni];
        int f = f0 + ni * 8 + 2 * tig;
        int n = n0 + gid;
        float bb0 = b2s[f], bb1 = b2s[f + 1];
        float m0 = msk_sh[n], m1 = msk_sh[n + 8];
        *(float2*)&h_s[n * HS + f]       = make_float2((d[0] + bb0) * m0, (d[1] + bb1) * m0);
        *(float2*)&h_s[(n + 8) * HS + f] = make_float2((d[2] + bb0) * m1, (d[3] + bb1) * m1);
    }
    __syncthreads();

    // ---- reduce: y[f] = sum_n Wm[n,f] * xw[nbr[n], f] (two 32-n halves) ----
    {
        const int half = tid >> 7, f = tid & 127;
        const float* xwb = g_xw + (size_t)b * A_DIM * F_DIM + f;
        float y = 0.0f;
#pragma unroll 8
        for (int j = 0; j < 32; ++j) {
            int n = half * 32 + j;
            float xv = __ldg(xwb + (size_t)nbr_sh[n] * F_DIM);
            y = fmaf(h_s[n * HS + f], xv, y);
        }
        y_sh[half * 128 + f] = y;
    }
    __syncthreads();
    if (tid < 128)
        g_y[(size_t)c * F_DIM + tid] = y_sh[tid] + y_sh[128 + tid];
}

// ---------------------------------------------------------------------------
// Inputs: x, pairwise_mask, neighbors, f_ij, W_f1, b_f1, W_f2, b_f2,
//         W_in2f, W_f2out, b_f2out
// ---------------------------------------------------------------------------
extern "C" void kernel_launch(void* const* d_in, const int* in_sizes, int n_in,
                              void* d_out, int out_size)
{
    const float* x      = (const float*)d_in[0];
    const float* mask   = (const float*)d_in[1];
    const int*   nbrs   = (const int*)  d_in[2];
    const float* f_ij   = (const float*)d_in[3];
    const float* W_f1   = (const float*)d_in[4];
    const float* b_f1   = (const float*)d_in[5];
    const float* W_f2   = (const float*)d_in[6];
    const float* b_f2   = (const float*)d_in[7];
    const float* W_in2f = (const float*)d_in[8];
    const float* W_out  = (const float*)d_in[9];
    const float* b_out  = (const float*)d_in[10];
    float*       out    = (float*)d_out;

    const int BA = in_sizes[0] / F_DIM;   // 8192

    static float* xw_ptr = nullptr;
    static float* y_ptr  = nullptr;
    if (!xw_ptr) { cudaGetSymbolAddress((void**)&xw_ptr, g_xw);
                   cudaGetSymbolAddress((void**)&y_ptr,  g_y); }

    cudaFuncSetAttribute(cfconv_mma, cudaFuncAttributeMaxDynamicSharedMemorySize, SMEM_TOTAL);

    prep_kernel<<<1, 256>>>(W_f1, W_f2);
    dense_kernel<<<BA / 8, F_DIM>>>(x, W_in2f, nullptr, xw_ptr, 0);     // xw = x @ W_in2f
    cfconv_mma<<<BA, 256, SMEM_TOTAL>>>(f_ij, mask, nbrs, b_f1, b_f2);
    dense_kernel<<<BA / 8, F_DIM>>>(y_ptr, W_out, b_out, out, 1);       // out = ssp(y @ W_out + b)
}